// round 16
// baseline (speedup 1.0000x reference)
#include <cuda_runtime.h>
#include <cuda_bf16.h>

// Problem constants (fixed by reference setup_inputs)
#define N_B      32
#define N_C      3
#define HW       4096      // 64*64
#define HW4      1024      // float4 per channel
#define N_EMBD   896
#define INNER    128
#define N_LVL    7
#define N_CLS    1000
#define ROOT_OFF 768       // 6 * INNER

#define NMEAN    64        // 2 half-blocks per batch
#define NCLSB    16        // 16 classifier blocks, 64 k each
#define NBLK     (NMEAN + NCLSB)   // 80 (one wave)
#define NTHR     512
#define KCH      64        // k per classifier block

// Scratch (__device__ globals; allocations forbidden). Counters monotonic =>
// generation = count/N is the launch index; valid on correctness call and
// every graph replay (stream-ordered launches).
// INVARIANT: exactly ONE publisher per 16B line (R13 regression lesson).
__device__ float4 g_half[NMEAN];            // {s0, s1, s2, tag_bits} raw half-sums
__device__ unsigned long long g_mean_ctr;   // +64 per launch
__device__ unsigned long long g_cls_ctr;    // +16 per launch

// ---------------------------------------------------------------------------
// One kernel, tagged-data sync (R12/R14 shape, half-warp split epilogue):
//  blocks 0..63  : batch b=blk>>1, half h=blk&1 — 24KB x slice, raw channel
//                  sums published as ONE tagged 16B stcg. EXIT.
//  blocks 64..79 : 64-k chunk — 32KB cls_w hoisted, emb_w collapse,
//                  sP={A+cls_b,W0,W1,W2}; lanes 0-15 of each warp own batch
//                  2w, lanes 16-31 own 2w+1: each lane polls 2 half-lines and
//                  emits ONE STG.128 (4 outputs).
// ---------------------------------------------------------------------------
__global__ __launch_bounds__(NTHR) void k_all(
    const float* __restrict__ x,
    const float* __restrict__ emb_w,
    const float* __restrict__ emb_b,
    const float* __restrict__ cls_w,
    const float* __restrict__ cls_b,
    float* __restrict__ out)
{
    const int tid  = threadIdx.x;
    const int blk  = blockIdx.x;
    const int lane = tid & 31;

    if (blk < NMEAN) {
        // ======================= mean half-blocks (publishers) ==============
        unsigned int tag = 0;
        if (tid == 0) {
            unsigned long long my = atomicAdd(&g_mean_ctr, 1ULL);
            tag = (unsigned int)(my / NMEAN) + 1u;     // overlaps x loads
        }
        const int b = blk >> 1, h = blk & 1;
        const float4* xb = (const float4*)(x + (size_t)b * (N_C * HW));
        const int off = h * 512 + tid;                 // half of each channel
        float s0, s1, s2;
        {
            float4 a = xb[0 * HW4 + off];
            float4 c = xb[1 * HW4 + off];
            float4 d = xb[2 * HW4 + off];
            s0 = (a.x + a.y) + (a.z + a.w);
            s1 = (c.x + c.y) + (c.z + c.w);
            s2 = (d.x + d.y) + (d.z + d.w);
        }
        #pragma unroll
        for (int o = 16; o > 0; o >>= 1) {
            s0 += __shfl_xor_sync(0xFFFFFFFFu, s0, o);
            s1 += __shfl_xor_sync(0xFFFFFFFFu, s1, o);
            s2 += __shfl_xor_sync(0xFFFFFFFFu, s2, o);
        }
        __shared__ float wr[16][3];
        const int wid = tid >> 5;
        if (lane == 0) { wr[wid][0] = s0; wr[wid][1] = s1; wr[wid][2] = s2; }
        __syncthreads();
        if (tid < 16) {
            float a0 = wr[tid][0], a1 = wr[tid][1], a2 = wr[tid][2];
            #pragma unroll
            for (int o = 8; o > 0; o >>= 1) {
                a0 += __shfl_xor_sync(0xFFFFu, a0, o);
                a1 += __shfl_xor_sync(0xFFFFu, a1, o);
                a2 += __shfl_xor_sync(0xFFFFu, a2, o);
            }
            if (tid == 0) {
                // raw half-sums + tag, one 16B sector, single writer
                float4 cf = make_float4(a0, a1, a2, __uint_as_float(tag));
                __stcg(&g_half[blk], cf);
            }
        }
        return;
    }

    // ======================= classifier (consumer) blocks ===================
    const int kq = blk - NMEAN;                        // 0..15
    const int t  = tid & 63;                           // k-lane (0..63)
    const int jg = tid >> 6;                           // j-group (0..7), 16 j each
    const int k  = kq * KCH + t;
    const int keff = (k < N_CLS) ? k : (N_CLS - 1);    // clamp OOB reads

    __shared__ unsigned int s_tag;
    if (tid == 0) {
        unsigned long long my = atomicAdd(&g_cls_ctr, 1ULL);
        s_tag = (unsigned int)(my / NCLSB) + 1u;       // overlaps loads below
    }

    // Hoist cls_w loads (16/thread, warp-coalesced: 32 consecutive keff)
    float wreg[16];
    float cbreg = 0.f;
    {
        const int jbase = jg * 16;
        #pragma unroll
        for (int jj = 0; jj < 16; jj++)
            wreg[jj] = __ldg(&cls_w[(jbase + jj) * N_CLS + keff]);
        if (jg == 0) cbreg = __ldg(&cls_b[keff]);
    }

    __shared__ float  sw[4][INNER];                    // [bias, ws0, ws1, ws2][j]
    __shared__ float  part[8][4][KCH];                 // [jg][A/W0/W1/W2][t]
    __shared__ float4 sP[KCH];                         // {A+cls_b, W0, W1, W2}

    if (tid < INNER) {
        float w0 = 0.f, w1 = 0.f, w2 = 0.f;
        #pragma unroll
        for (int l = 0; l < N_LVL; l++) {
            w0 += emb_w[(3 * l + 0) * N_EMBD + ROOT_OFF + tid];
            w1 += emb_w[(3 * l + 1) * N_EMBD + ROOT_OFF + tid];
            w2 += emb_w[(3 * l + 2) * N_EMBD + ROOT_OFF + tid];
        }
        sw[0][tid] = emb_b[ROOT_OFF + tid];
        sw[1][tid] = w0;  sw[2][tid] = w1;  sw[3][tid] = w2;
    }
    __syncthreads();

    float aA = 0.f, a0 = 0.f, a1 = 0.f, a2 = 0.f;
    {
        const int jbase = jg * 16;
        #pragma unroll
        for (int jj = 0; jj < 16; jj++) {
            const float w = wreg[jj];
            aA = fmaf(sw[0][jbase + jj], w, aA);
            a0 = fmaf(sw[1][jbase + jj], w, a0);
            a1 = fmaf(sw[2][jbase + jj], w, a1);
            a2 = fmaf(sw[3][jbase + jj], w, a2);
        }
    }
    part[jg][0][t] = (jg == 0) ? aA + cbreg : aA;      // fold cls_b into A
    part[jg][1][t] = a0;
    part[jg][2][t] = a1;
    part[jg][3][t] = a2;
    __syncthreads();

    // Widened tail reduce: 256 threads, thread = (component, k-lane), 8 adds.
    if (tid < 4 * KCH) {
        const int comp = tid >> 6;                     // 0..3
        const int tt   = tid & 63;
        float v = 0.f;
        #pragma unroll
        for (int g = 0; g < 8; g++) v += part[g][comp][tt];
        ((float*)&sP[tt])[comp] = v;
    }
    __syncthreads();                                   // sP + s_tag visible

    // Half-warp split epilogue: lanes 0-15 -> batch 2w, lanes 16-31 -> 2w+1.
    // Each lane polls ITS batch's 2 half-lines, then one STG.128 (4 outputs).
    const unsigned int tag = s_tag;
    const int wax  = tid >> 5;                         // warp index (0..15)
    const int half = lane >> 4;                        // 0 or 1
    const int lq   = lane & 15;                        // quad index within batch
    const int b    = wax * 2 + half;
    const float4* hp = &g_half[b * 2];                 // this batch's 2 halves
    float h0x,h0y,h0z,h0w, h1x,h1y,h1z,h1w;
    do {
        asm volatile("ld.global.cg.v4.f32 {%0,%1,%2,%3}, [%4];"
                     : "=f"(h0x),"=f"(h0y),"=f"(h0z),"=f"(h0w)
                     : "l"(hp + 0) : "memory");
        asm volatile("ld.global.cg.v4.f32 {%0,%1,%2,%3}, [%4];"
                     : "=f"(h1x),"=f"(h1y),"=f"(h1z),"=f"(h1w)
                     : "l"(hp + 1) : "memory");
    } while (__float_as_uint(h0w) != tag || __float_as_uint(h1w) != tag);

    const int kbase = kq * KCH + lq * 4;
    if (kbase < N_CLS) {                               // 1000 % 4 == 0 => no straddle
        const float inv = 1.0f / HW;
        const float c0 = (h0x + h1x) * inv;
        const float c1 = (h0y + h1y) * inv;
        const float c2 = (h0z + h1z) * inv;
        const float4 P0 = sP[lq * 4 + 0];
        const float4 P1 = sP[lq * 4 + 1];
        const float4 P2 = sP[lq * 4 + 2];
        const float4 P3 = sP[lq * 4 + 3];
        float4 o;
        o.x = P0.x + fmaf(c0, P0.y, fmaf(c1, P0.z, c2 * P0.w));
        o.y = P1.x + fmaf(c0, P1.y, fmaf(c1, P1.z, c2 * P1.w));
        o.z = P2.x + fmaf(c0, P2.y, fmaf(c1, P2.z, c2 * P2.w));
        o.w = P3.x + fmaf(c0, P3.y, fmaf(c1, P3.z, c2 * P3.w));
        *(float4*)(out + (size_t)b * N_CLS + kbase) = o;
    }
}

// ---------------------------------------------------------------------------
// Launch. Inputs (metadata order): x, emb_w, emb_b, cls_w, cls_b. Output f32.
// Graph-capturable: one kernel launch, no allocs, no syncs.
// ---------------------------------------------------------------------------
extern "C" void kernel_launch(void* const* d_in, const int* in_sizes, int n_in,
                              void* d_out, int out_size)
{
    const float* x     = (const float*)d_in[0];
    const float* emb_w = (const float*)d_in[1];
    const float* emb_b = (const float*)d_in[2];
    const float* cls_w = (const float*)d_in[3];
    const float* cls_b = (const float*)d_in[4];
    float* out = (float*)d_out;

    k_all<<<NBLK, NTHR>>>(x, emb_w, emb_b, cls_w, cls_b, out);
}

// round 17
// speedup vs baseline: 1.3077x; 1.3077x over previous
#include <cuda_runtime.h>
#include <cuda_bf16.h>

// Problem constants (fixed by reference setup_inputs)
#define N_B      32
#define N_C      3
#define HW       4096      // 64*64
#define HW4      1024      // float4 per channel
#define N_EMBD   896
#define INNER    128
#define N_LVL    7
#define N_CLS    1000
#define ROOT_OFF 768       // 6 * INNER

#define NMEAN    64        // 2 half-blocks per batch
#define NCLSB    16        // 16 classifier blocks, 64 k each
#define NBLK     (NMEAN + NCLSB)   // 80 (one wave)
#define NTHR     256       // halved: lighter ramp, MLP up per thread
#define KCH      64        // k per classifier block

// Scratch (__device__ globals; allocations forbidden). Counters monotonic =>
// generation = count/N is the launch index; valid on correctness call and
// every graph replay (stream-ordered launches).
// INVARIANT: exactly ONE publisher per 16B line (R13 regression lesson).
__device__ float4 g_half[NMEAN];            // {s0, s1, s2, tag_bits} raw half-sums
__device__ unsigned long long g_mean_ctr;   // +64 per launch
__device__ unsigned long long g_cls_ctr;    // +16 per launch

// ---------------------------------------------------------------------------
// One kernel, tagged-data sync, 256-thread blocks:
//  blocks 0..63  : batch b=blk>>1, half h=blk&1 — 24KB x slice (6 float4 per
//                  thread, MLP=6), raw channel sums in ONE tagged 16B stcg.
//  blocks 64..79 : 64-k chunk — 32KB cls_w hoisted (32/thread), emb_w
//                  collapse, sP={A+cls_b,W0,W1,W2}; 8 warps, half-warp owns
//                  2 batches: poll 4 single-writer lines, 2x STG.128.
// ---------------------------------------------------------------------------
__global__ __launch_bounds__(NTHR) void k_all(
    const float* __restrict__ x,
    const float* __restrict__ emb_w,
    const float* __restrict__ emb_b,
    const float* __restrict__ cls_w,
    const float* __restrict__ cls_b,
    float* __restrict__ out)
{
    const int tid  = threadIdx.x;
    const int blk  = blockIdx.x;
    const int lane = tid & 31;

    if (blk < NMEAN) {
        // ======================= mean half-blocks (publishers) ==============
        unsigned int tag = 0;
        if (tid == 0) {
            unsigned long long my = atomicAdd(&g_mean_ctr, 1ULL);
            tag = (unsigned int)(my / NMEAN) + 1u;     // overlaps x loads
        }
        const int b = blk >> 1, h = blk & 1;
        const float4* xb = (const float4*)(x + (size_t)b * (N_C * HW));
        const int off = h * 512 + tid;                 // [h*512, h*512+512)
        float s0, s1, s2;
        {
            float4 a0 = xb[0 * HW4 + off], a1 = xb[0 * HW4 + off + 256];
            float4 c0 = xb[1 * HW4 + off], c1 = xb[1 * HW4 + off + 256];
            float4 d0 = xb[2 * HW4 + off], d1 = xb[2 * HW4 + off + 256];
            s0 = ((a0.x + a0.y) + (a0.z + a0.w)) + ((a1.x + a1.y) + (a1.z + a1.w));
            s1 = ((c0.x + c0.y) + (c0.z + c0.w)) + ((c1.x + c1.y) + (c1.z + c1.w));
            s2 = ((d0.x + d0.y) + (d0.z + d0.w)) + ((d1.x + d1.y) + (d1.z + d1.w));
        }
        #pragma unroll
        for (int o = 16; o > 0; o >>= 1) {
            s0 += __shfl_xor_sync(0xFFFFFFFFu, s0, o);
            s1 += __shfl_xor_sync(0xFFFFFFFFu, s1, o);
            s2 += __shfl_xor_sync(0xFFFFFFFFu, s2, o);
        }
        __shared__ float wr[8][3];
        const int wid = tid >> 5;
        if (lane == 0) { wr[wid][0] = s0; wr[wid][1] = s1; wr[wid][2] = s2; }
        __syncthreads();
        if (tid < 8) {
            float a0 = wr[tid][0], a1 = wr[tid][1], a2 = wr[tid][2];
            #pragma unroll
            for (int o = 4; o > 0; o >>= 1) {
                a0 += __shfl_xor_sync(0xFFu, a0, o);
                a1 += __shfl_xor_sync(0xFFu, a1, o);
                a2 += __shfl_xor_sync(0xFFu, a2, o);
            }
            if (tid == 0) {
                // raw half-sums + tag, one 16B sector, single writer
                float4 cf = make_float4(a0, a1, a2, __uint_as_float(tag));
                __stcg(&g_half[blk], cf);
            }
        }
        return;
    }

    // ======================= classifier (consumer) blocks ===================
    const int kq = blk - NMEAN;                        // 0..15
    const int t  = tid & 63;                           // k-lane (0..63)
    const int jg = tid >> 6;                           // j-group (0..3), 32 j each
    const int k  = kq * KCH + t;
    const int keff = (k < N_CLS) ? k : (N_CLS - 1);    // clamp OOB reads

    __shared__ unsigned int s_tag;
    if (tid == 0) {
        unsigned long long my = atomicAdd(&g_cls_ctr, 1ULL);
        s_tag = (unsigned int)(my / NCLSB) + 1u;       // overlaps loads below
    }

    // Hoist cls_w loads (32/thread, warp-coalesced: 32 consecutive keff)
    float wreg[32];
    float cbreg = 0.f;
    {
        const int jbase = jg * 32;
        #pragma unroll
        for (int jj = 0; jj < 32; jj++)
            wreg[jj] = __ldg(&cls_w[(jbase + jj) * N_CLS + keff]);
        if (jg == 0) cbreg = __ldg(&cls_b[keff]);
    }

    __shared__ float  sw[4][INNER];                    // [bias, ws0, ws1, ws2][j]
    __shared__ float  part[4][4][KCH];                 // [jg][A/W0/W1/W2][t]
    __shared__ float4 sP[KCH];                         // {A+cls_b, W0, W1, W2}

    if (tid < INNER) {
        float w0 = 0.f, w1 = 0.f, w2 = 0.f;
        #pragma unroll
        for (int l = 0; l < N_LVL; l++) {
            w0 += emb_w[(3 * l + 0) * N_EMBD + ROOT_OFF + tid];
            w1 += emb_w[(3 * l + 1) * N_EMBD + ROOT_OFF + tid];
            w2 += emb_w[(3 * l + 2) * N_EMBD + ROOT_OFF + tid];
        }
        sw[0][tid] = emb_b[ROOT_OFF + tid];
        sw[1][tid] = w0;  sw[2][tid] = w1;  sw[3][tid] = w2;
    }
    __syncthreads();

    float aA = 0.f, a0 = 0.f, a1 = 0.f, a2 = 0.f;
    {
        const int jbase = jg * 32;
        #pragma unroll
        for (int jj = 0; jj < 32; jj++) {
            const float w = wreg[jj];
            aA = fmaf(sw[0][jbase + jj], w, aA);
            a0 = fmaf(sw[1][jbase + jj], w, a0);
            a1 = fmaf(sw[2][jbase + jj], w, a1);
            a2 = fmaf(sw[3][jbase + jj], w, a2);
        }
    }
    part[jg][0][t] = (jg == 0) ? aA + cbreg : aA;      // fold cls_b into A
    part[jg][1][t] = a0;
    part[jg][2][t] = a1;
    part[jg][3][t] = a2;
    __syncthreads();

    // Tail reduce: all 256 threads, thread = (component, k-lane), 4 adds.
    {
        const int comp = tid >> 6;                     // 0..3
        const int tt   = tid & 63;
        float v = 0.f;
        #pragma unroll
        for (int g = 0; g < 4; g++) v += part[g][comp][tt];
        ((float*)&sP[tt])[comp] = v;
    }
    __syncthreads();                                   // sP + s_tag visible

    // Epilogue: 8 warps; half-warp owns 2 batches. Lane polls its batches'
    // 4 single-writer lines, then 2x STG.128 (8 outputs).
    const unsigned int tag = s_tag;
    const int wax  = tid >> 5;                         // warp index (0..7)
    const int half = lane >> 4;                        // 0 or 1
    const int lq   = lane & 15;                        // quad index within batch
    const int b0   = wax * 4 + half * 2;               // first of 2 owned batches
    const float4* hp = &g_half[b0 * 2];                // 4 half-lines
    float h0x,h0y,h0z,h0w, h1x,h1y,h1z,h1w, h2x,h2y,h2z,h2w, h3x,h3y,h3z,h3w;
    do {
        asm volatile("ld.global.cg.v4.f32 {%0,%1,%2,%3}, [%4];"
                     : "=f"(h0x),"=f"(h0y),"=f"(h0z),"=f"(h0w)
                     : "l"(hp + 0) : "memory");
        asm volatile("ld.global.cg.v4.f32 {%0,%1,%2,%3}, [%4];"
                     : "=f"(h1x),"=f"(h1y),"=f"(h1z),"=f"(h1w)
                     : "l"(hp + 1) : "memory");
        asm volatile("ld.global.cg.v4.f32 {%0,%1,%2,%3}, [%4];"
                     : "=f"(h2x),"=f"(h2y),"=f"(h2z),"=f"(h2w)
                     : "l"(hp + 2) : "memory");
        asm volatile("ld.global.cg.v4.f32 {%0,%1,%2,%3}, [%4];"
                     : "=f"(h3x),"=f"(h3y),"=f"(h3z),"=f"(h3w)
                     : "l"(hp + 3) : "memory");
    } while (__float_as_uint(h0w) != tag || __float_as_uint(h1w) != tag ||
             __float_as_uint(h2w) != tag || __float_as_uint(h3w) != tag);

    const int kbase = kq * KCH + lq * 4;
    if (kbase < N_CLS) {                               // 1000 % 4 == 0 => no straddle
        const float inv = 1.0f / HW;
        const float4 P0 = sP[lq * 4 + 0];
        const float4 P1 = sP[lq * 4 + 1];
        const float4 P2 = sP[lq * 4 + 2];
        const float4 P3 = sP[lq * 4 + 3];
        {   // batch b0 (halves 0,1)
            const float c0 = (h0x + h1x) * inv;
            const float c1 = (h0y + h1y) * inv;
            const float c2 = (h0z + h1z) * inv;
            float4 o;
            o.x = P0.x + fmaf(c0, P0.y, fmaf(c1, P0.z, c2 * P0.w));
            o.y = P1.x + fmaf(c0, P1.y, fmaf(c1, P1.z, c2 * P1.w));
            o.z = P2.x + fmaf(c0, P2.y, fmaf(c1, P2.z, c2 * P2.w));
            o.w = P3.x + fmaf(c0, P3.y, fmaf(c1, P3.z, c2 * P3.w));
            *(float4*)(out + (size_t)b0 * N_CLS + kbase) = o;
        }
        {   // batch b0+1 (halves 2,3)
            const float c0 = (h2x + h3x) * inv;
            const float c1 = (h2y + h3y) * inv;
            const float c2 = (h2z + h3z) * inv;
            float4 o;
            o.x = P0.x + fmaf(c0, P0.y, fmaf(c1, P0.z, c2 * P0.w));
            o.y = P1.x + fmaf(c0, P1.y, fmaf(c1, P1.z, c2 * P1.w));
            o.z = P2.x + fmaf(c0, P2.y, fmaf(c1, P2.z, c2 * P2.w));
            o.w = P3.x + fmaf(c0, P3.y, fmaf(c1, P3.z, c2 * P3.w));
            *(float4*)(out + (size_t)(b0 + 1) * N_CLS + kbase) = o;
        }
    }
}

// ---------------------------------------------------------------------------
// Launch. Inputs (metadata order): x, emb_w, emb_b, cls_w, cls_b. Output f32.
// Graph-capturable: one kernel launch, no allocs, no syncs.
// ---------------------------------------------------------------------------
extern "C" void kernel_launch(void* const* d_in, const int* in_sizes, int n_in,
                              void* d_out, int out_size)
{
    const float* x     = (const float*)d_in[0];
    const float* emb_w = (const float*)d_in[1];
    const float* emb_b = (const float*)d_in[2];
    const float* cls_w = (const float*)d_in[3];
    const float* cls_b = (const float*)d_in[4];
    float* out = (float*)d_out;

    k_all<<<NBLK, NTHR>>>(x, emb_w, emb_b, cls_w, cls_b, out);
}